// round 8
// baseline (speedup 1.0000x reference)
#include <cuda_runtime.h>
#include <cuda_bf16.h>
#include <cstdint>

// Problem constants
#define BS   64
#define IC   256     // in_dim (GEMM K)
#define NPIX 256     // 16*16 pixels
#define J    64      // out caps
#define D2   32      // dim per cap
#define OUT  2048    // J*D2

#define NCH  16      // routing i-chunks
#define CHI  16      // pixels per chunk

// pred layout: [b][j][i][d]
__device__ float g_pred[(size_t)BS * J * NPIX * D2];      // 134 MB
__device__ float g_L[(size_t)BS * J * NPIX];              // logits after iter-1
__device__ float g_spart[(size_t)BS * NCH * J * D2];      // partial s
__device__ float g_v[(size_t)BS * J * D2];                // v between iters

// bf16 hi/lo split operands
__device__ __nv_bfloat16 g_Wh[(size_t)OUT * IC];
__device__ __nv_bfloat16 g_Wl[(size_t)OUT * IC];
__device__ __nv_bfloat16 g_Xh[(size_t)BS * NPIX * IC];    // [b][i][ic] (K-major)
__device__ __nv_bfloat16 g_Xl[(size_t)BS * NPIX * IC];

// ---------------------------------------------------------------------------
// Helpers (baseline PTX only — valid on compute_103)
// ---------------------------------------------------------------------------
__device__ __forceinline__ uint32_t smem_u32(const void* p) {
    uint32_t a;
    asm("{ .reg .u64 t; cvta.to.shared.u64 t, %1; cvt.u32.u64 %0, t; }"
        : "=r"(a) : "l"(p));
    return a;
}
__device__ __forceinline__ void ldsm4(uint32_t& r0, uint32_t& r1,
                                      uint32_t& r2, uint32_t& r3, uint32_t addr) {
    asm volatile("ldmatrix.sync.aligned.m8n8.x4.shared.b16 {%0,%1,%2,%3}, [%4];"
                 : "=r"(r0), "=r"(r1), "=r"(r2), "=r"(r3) : "r"(addr));
}
__device__ __forceinline__ void mma_bf16(float* c, const uint32_t* a,
                                         uint32_t b0, uint32_t b1) {
    asm volatile(
        "mma.sync.aligned.m16n8k16.row.col.f32.bf16.bf16.f32 "
        "{%0,%1,%2,%3}, {%4,%5,%6,%7}, {%8,%9}, {%0,%1,%2,%3};"
        : "+f"(c[0]), "+f"(c[1]), "+f"(c[2]), "+f"(c[3])
        : "r"(a[0]), "r"(a[1]), "r"(a[2]), "r"(a[3]), "r"(b0), "r"(b1));
}

#define SWZ(o) ((o) ^ (((o) >> 3) & 0x70))

// ---------------------------------------------------------------------------
// Conversion kernels: fp32 -> bf16 hi/lo split
// ---------------------------------------------------------------------------
__global__ __launch_bounds__(256) void conv_w(const float* __restrict__ W) {
    int i = blockIdx.x * 256 + threadIdx.x;
    float v = W[i];
    __nv_bfloat16 h = __float2bfloat16(v);
    g_Wh[i] = h;
    g_Wl[i] = __float2bfloat16(v - __bfloat162float(h));
}

__global__ __launch_bounds__(256) void conv_x(const float* __restrict__ x) {
    __shared__ float t[32][33];
    int b   = blockIdx.z;
    int i0  = blockIdx.x * 32;
    int ic0 = blockIdx.y * 32;
    int tx = threadIdx.x, ty = threadIdx.y;   // 32 x 8
    #pragma unroll
    for (int q = 0; q < 4; q++)
        t[ty + q * 8][tx] = x[((size_t)b * IC + ic0 + ty + q * 8) * NPIX + i0 + tx];
    __syncthreads();
    #pragma unroll
    for (int q = 0; q < 4; q++) {
        float v = t[tx][ty + q * 8];
        __nv_bfloat16 h = __float2bfloat16(v);
        size_t o = ((size_t)b * NPIX + i0 + ty + q * 8) * IC + ic0 + tx;
        g_Xh[o] = h;
        g_Xl[o] = __float2bfloat16(v - __bfloat162float(h));
    }
}

// ---------------------------------------------------------------------------
// GEMM via mma.sync bf16 hi/lo split.
// Per CTA: M=128(o) x N=128(i), K=256 in 4 chunks of 64.
// 8 warps: warp_m = wid>>2 (2), warp_n = wid&3 (4); warp tile 64x32.
// smem per chunk: Ah|Al|Bh|Bl, each 128 rows x 128B (SW128 swizzled) = 64 KB.
// ---------------------------------------------------------------------------
#define GSMEM 65536

__global__ __launch_bounds__(256, 1) void gemm_mma(const float* __restrict__ Wbias) {
    extern __shared__ char smem[];
    const uint32_t sb = smem_u32(smem);

    const int b    = blockIdx.z;
    const int o0   = blockIdx.x * 128;
    const int i0   = blockIdx.y * 128;
    const int tid  = threadIdx.x;
    const int wid  = tid >> 5;
    const int lane = tid & 31;
    const int wm   = wid >> 2;           // 0..1  (M)
    const int wn   = wid & 3;            // 0..3  (N)

    const __nv_bfloat16* xh = g_Xh + (size_t)b * NPIX * IC;
    const __nv_bfloat16* xl = g_Xl + (size_t)b * NPIX * IC;

    float acc[4][4][4];                  // [mt][nt][e]
    #pragma unroll
    for (int mt = 0; mt < 4; mt++)
        #pragma unroll
        for (int nt = 0; nt < 4; nt++)
            #pragma unroll
            for (int e = 0; e < 4; e++) acc[mt][nt][e] = 0.f;

    // per-thread ldmatrix row addressing: row = lane&15, half = lane>>4
    const int lrow = lane & 15;
    const uint32_t lhalf = (uint32_t)(lane >> 4) * 16;

    for (int c = 0; c < 4; c++) {
        // ---- cooperative load of Ah|Al|Bh|Bl (swizzled) ----
        #pragma unroll
        for (int q = 0; q < 4; q++) {
            int idx = tid + q * 256;              // 0..1023
            int row = idx >> 3, seg = idx & 7;
            uint32_t sw = SWZ((uint32_t)(row * 128 + seg * 16));
            size_t wsrc = (size_t)(o0 + row) * IC + c * 64 + seg * 8;
            size_t xsrc = (size_t)(i0 + row) * IC + c * 64 + seg * 8;
            *(uint4*)(smem +          sw) = *(const uint4*)(g_Wh + wsrc);
            *(uint4*)(smem + 16384u + sw) = *(const uint4*)(g_Wl + wsrc);
            *(uint4*)(smem + 32768u + sw) = *(const uint4*)(xh + xsrc);
            *(uint4*)(smem + 49152u + sw) = *(const uint4*)(xl + xsrc);
        }
        __syncthreads();

        #pragma unroll
        for (int ks = 0; ks < 4; ks++) {
            const uint32_t koff = lhalf + (uint32_t)ks * 32;

            // B frags: 2 x ldmatrix.x4 per version (covers nt pairs)
            uint32_t bh[4][2], bl[4][2];
            #pragma unroll
            for (int p = 0; p < 2; p++) {
                int brow = wn * 32 + p * 16 + lrow;
                uint32_t off = SWZ((uint32_t)(brow * 128) + koff);
                uint32_t r0, r1, r2, r3;
                ldsm4(r0, r1, r2, r3, sb + 32768u + off);
                bh[p * 2 + 0][0] = r0; bh[p * 2 + 0][1] = r2;
                bh[p * 2 + 1][0] = r1; bh[p * 2 + 1][1] = r3;
                ldsm4(r0, r1, r2, r3, sb + 49152u + off);
                bl[p * 2 + 0][0] = r0; bl[p * 2 + 0][1] = r2;
                bl[p * 2 + 1][0] = r1; bl[p * 2 + 1][1] = r3;
            }

            // A frags + MMAs per mt
            #pragma unroll
            for (int mt = 0; mt < 4; mt++) {
                int arow = wm * 64 + mt * 16 + lrow;
                uint32_t off = SWZ((uint32_t)(arow * 128) + koff);
                uint32_t ah[4], al[4];
                ldsm4(ah[0], ah[1], ah[2], ah[3], sb + off);
                ldsm4(al[0], al[1], al[2], al[3], sb + 16384u + off);
                #pragma unroll
                for (int nt = 0; nt < 4; nt++) {
                    mma_bf16(acc[mt][nt], ah, bh[nt][0], bh[nt][1]);
                    mma_bf16(acc[mt][nt], ah, bl[nt][0], bl[nt][1]);
                    mma_bf16(acc[mt][nt], al, bh[nt][0], bh[nt][1]);
                }
            }
        }
        __syncthreads();
    }

    // ---- Epilogue: 4 chunks of 32 o-rows, staged via smem ----
    float (*Cs)[129] = reinterpret_cast<float (*)[129]>(smem);   // 32 x 129
    #pragma unroll
    for (int ch = 0; ch < 4; ch++) {
        if (wm == (ch >> 1)) {
            #pragma unroll
            for (int ml = 0; ml < 2; ml++) {
                int mt = (ch & 1) * 2 + ml;
                #pragma unroll
                for (int nt = 0; nt < 4; nt++) {
                    #pragma unroll
                    for (int e = 0; e < 4; e++) {
                        int o_l = ml * 16 + (lane >> 2) + (e >> 1) * 8;
                        int i_l = wn * 32 + nt * 8 + (lane & 3) * 2 + (e & 1);
                        Cs[o_l][i_l] = acc[mt][nt][e];
                    }
                }
            }
        }
        __syncthreads();
        // coalesced write-out: per i, 32 contiguous d
        int jg = (o0 >> 5) + ch;
        for (int e = tid; e < 32 * 128; e += 256) {
            int i_l = e >> 5;
            int o_l = e & 31;
            size_t dst = (((size_t)b * J + jg) * NPIX + (i0 + i_l)) * D2 + o_l;
            g_pred[dst] = Cs[o_l][i_l] + Wbias[o0 + ch * 32 + o_l];
        }
        __syncthreads();
    }
}

// ---------------------------------------------------------------------------
// Routing sweep: one CTA per (b, i-chunk of 16 pixels).
// ---------------------------------------------------------------------------
#define LCP 17

__global__ __launch_bounds__(512) void route_kernel(
    const float* __restrict__ b_init, int it)
{
    __shared__ float Lc[J * LCP];
    __shared__ float vbuf[J * D2];
    __shared__ float cbuf[J * CHI];
    __shared__ float mx[CHI], rd[CHI];

    const int ch  = blockIdx.x;
    const int b   = blockIdx.y;
    const int i0  = ch * CHI;
    const int tid = threadIdx.x;
    const int w   = tid >> 5;
    const int lane = tid & 31;

    const float* Lsrc = (it == 2) ? g_L : b_init;

    for (int e = tid; e < J * CHI; e += 512) {
        int j = e >> 4, ii = e & 15;
        Lc[j * LCP + ii] = Lsrc[((size_t)b * J + j) * NPIX + i0 + ii];
    }
    if (it) {
        for (int e = tid; e < J * D2; e += 512)
            vbuf[e] = g_v[(size_t)b * J * D2 + e];
    }
    __syncthreads();

    // Phase D: db[j,i] = v_j . P[j,i,:]
    if (it) {
        int i_l = lane & 15, h = lane >> 4;
        #pragma unroll
        for (int jj = 0; jj < 4; jj++) {
            int j = w * 4 + jj;
            const float4* p4 = reinterpret_cast<const float4*>(
                g_pred + (((size_t)b * J + j) * NPIX + i0 + i_l) * D2 + h * 16);
            const float4* v4 = reinterpret_cast<const float4*>(vbuf + j * D2 + h * 16);
            float acc = 0.f;
            #pragma unroll
            for (int u = 0; u < 4; u++) {
                float4 p = p4[u], v = v4[u];
                acc += p.x * v.x + p.y * v.y + p.z * v.z + p.w * v.w;
            }
            acc += __shfl_xor_sync(0xFFFFFFFFu, acc, 16);
            if (h == 0) {
                float nl = Lc[j * LCP + i_l] + acc;
                Lc[j * LCP + i_l] = nl;
                if (it == 1)
                    g_L[((size_t)b * J + j) * NPIX + i0 + i_l] = nl;
            }
        }
        __syncthreads();
    }

    // Softmax stats over J per pixel (warp w owns pixel w)
    {
        float v0 = Lc[lane * LCP + w];
        float v1 = Lc[(lane + 32) * LCP + w];
        float m = fmaxf(v0, v1);
        #pragma unroll
        for (int o = 16; o; o >>= 1) m = fmaxf(m, __shfl_xor_sync(0xFFFFFFFFu, m, o));
        float sum = __expf(v0 - m) + __expf(v1 - m);
        #pragma unroll
        for (int o = 16; o; o >>= 1) sum += __shfl_xor_sync(0xFFFFFFFFu, sum, o);
        if (lane == 0) { mx[w] = m; rd[w] = 1.0f / sum; }
    }
    __syncthreads();

    for (int e = tid; e < J * CHI; e += 512) {
        int j = e >> 4, ii = e & 15;
        cbuf[e] = __expf(Lc[j * LCP + ii] - mx[ii]) * rd[ii];
    }
    __syncthreads();

    // Phase B: partial s[j][d]
    #pragma unroll
    for (int jj = 0; jj < 4; jj++) {
        int j = w * 4 + jj;
        const float* Pj = g_pred + (((size_t)b * J + j) * NPIX + i0) * D2;
        const float* Cj = cbuf + j * CHI;
        float acc = 0.f;
        #pragma unroll
        for (int ii = 0; ii < CHI; ii++)
            acc = fmaf(Cj[ii], Pj[ii * D2 + lane], acc);
        g_spart[(((size_t)b * NCH + ch) * J + j) * D2 + lane] = acc;
    }
}

// ---------------------------------------------------------------------------
// Sum partials + squash. One warp per (b, j).
// ---------------------------------------------------------------------------
__global__ __launch_bounds__(256) void squash_kernel(float* __restrict__ out, int final_it)
{
    int gw   = blockIdx.x * 8 + (threadIdx.x >> 5);
    int b    = gw >> 6;
    int j    = gw & 63;
    int lane = threadIdx.x & 31;

    float s = 0.f;
    const float* base = g_spart + (((size_t)b * NCH) * J + j) * D2 + lane;
    #pragma unroll
    for (int ch = 0; ch < NCH; ch++)
        s += base[(size_t)ch * J * D2];

    float sq = s * s;
    #pragma unroll
    for (int o = 16; o; o >>= 1) sq += __shfl_xor_sync(0xFFFFFFFFu, sq, o);
    float scale = (sq / (1.0f + sq)) * rsqrtf(sq + 1e-8f);
    float v = scale * s;

    if (final_it) out[((size_t)b * J + j) * D2 + lane] = v;
    else          g_v[((size_t)b * J + j) * D2 + lane] = v;
}

// ---------------------------------------------------------------------------
// Launch
// Inputs: x[64,256,16,16] f32, b_init[64,64,256] f32, W[2048,256] f32, Wb[2048] f32
// ---------------------------------------------------------------------------
extern "C" void kernel_launch(void* const* d_in, const int* in_sizes, int n_in,
                              void* d_out, int out_size)
{
    const float* x      = (const float*)d_in[0];
    const float* b_init = (const float*)d_in[1];
    const float* W      = (const float*)d_in[2];
    const float* Wb     = (const float*)d_in[3];
    float* out = (float*)d_out;

    conv_w<<<(OUT * IC) / 256, 256>>>(W);
    conv_x<<<dim3(8, 8, BS), dim3(32, 8)>>>(x);

    cudaFuncSetAttribute(gemm_mma, cudaFuncAttributeMaxDynamicSharedMemorySize, GSMEM);
    dim3 ggrid(OUT / 128, NPIX / 128, BS);        // 16 x 2 x 64
    gemm_mma<<<ggrid, 256, GSMEM>>>(Wb);

    dim3 rgrid(NCH, BS);
    route_kernel<<<rgrid, 512>>>(b_init, 0);
    squash_kernel<<<512, 256>>>(out, 0);
    route_kernel<<<rgrid, 512>>>(b_init, 1);
    squash_kernel<<<512, 256>>>(out, 0);
    route_kernel<<<rgrid, 512>>>(b_init, 2);
    squash_kernel<<<512, 256>>>(out, 1);
}

// round 9
// speedup vs baseline: 1.8213x; 1.8213x over previous
#include <cuda_runtime.h>
#include <cstdint>

// Problem constants
#define BS   64
#define IC   256     // in_dim
#define NPIX 256     // pixels (I)
#define J    64      // out caps
#define D2   32      // dim per cap
#define NCHK 4       // i-chunks per batch in YD
#define CW   64      // chunk width (pixels)

// Global scratch (tiny — pred is never materialized)
__device__ float g_L[(size_t)BS * J * NPIX];            // 4 MB  logits after iter-1
__device__ float g_ypart[(size_t)BS * NCHK * J * IC];   // 16.8 MB [b][ch][j][ic]
__device__ float g_cpart[(size_t)BS * NCHK * J];        // [b][ch][j]
__device__ float g_wt[(size_t)BS * J * IC];             // 4 MB  [b][j][ic]
__device__ float g_beta[(size_t)BS * J];                // [b][j]

// ---------------------------------------------------------------------------
// f32x2 helpers (proven in R5 on this harness)
// ---------------------------------------------------------------------------
#define FFMA2(acc, aa, bb) \
    asm("fma.rn.f32x2 %0, %1, %2, %0;" : "+l"(acc) : "l"(aa), "l"(bb))
__device__ __forceinline__ unsigned long long dup2f(float s) {
    unsigned long long d;
    asm("mov.b64 %0, {%1, %1};" : "=l"(d) : "f"(s));
    return d;
}
__device__ __forceinline__ float2 unpk(unsigned long long v) {
    float2 r;
    asm("mov.b64 {%0, %1}, %2;" : "=f"(r.x), "=f"(r.y) : "l"(v));
    return r;
}

// SMEM float offsets for yd_kernel
#define XS_O   0                 // xs [ic=256][i=64]          16384
#define XT_O   16384             // xT [i=64][ic=256]          16384
#define WTS_O  32768             // wts [ic=256][j=64]         16384
#define CS_O   49152             // cs [i=64][j pad 65]        4160 (aliases aux)
#define LC_O   53312             // Lc [j=64][i pad 65]        4160
#define PM_O   57472             // 4x64
#define PS_O   57728             // 4x64
#define SM_FLOATS 57984          // 231,936 bytes

// ---------------------------------------------------------------------------
// YD kernel: one CTA per (i-chunk, b).
// it==0:  Lc = b_init;             softmax; y partials
// it==1:  db = wt.x+beta; L=b_init+db (store g_L); softmax; y partials
// it==2:  db = wt.x+beta; L=g_L+db;                softmax; y partials
// ---------------------------------------------------------------------------
__global__ __launch_bounds__(256, 1) void yd_kernel(
    const float* __restrict__ x, const float* __restrict__ b_init, int it)
{
    extern __shared__ float sm[];
    float* xs  = sm + XS_O;
    float* xT  = sm + XT_O;
    float* wts = sm + WTS_O;
    float* cs  = sm + CS_O;
    float* Lc  = sm + LC_O;
    float* pm  = sm + PM_O;
    float* ps  = sm + PS_O;
    float* aux = sm + CS_O;     // 2 x (32x33) tiles, used before cs is live

    const int ch  = blockIdx.x;
    const int b   = blockIdx.y;
    const int i0g = ch * CW;
    const int tid = threadIdx.x;

    // ---- load x chunk: xs[ic][i] (coalesced) ----
    const float* xb = x + (size_t)b * IC * NPIX + i0g;
    for (int e = tid; e < IC * CW; e += 256) {
        int ic = e >> 6, il = e & 63;
        xs[ic * 64 + il] = xb[(size_t)ic * NPIX + il];
    }
    // Lc for it==0 directly from b_init
    if (it == 0) {
        for (int e = tid; e < J * CW; e += 256) {
            int j = e >> 6, il = e & 63;
            Lc[j * 65 + il] = b_init[((size_t)b * J + j) * NPIX + i0g + il];
        }
    }
    __syncthreads();

    // ---- transpose xs -> xT via padded 32x32 tiles (2 tiles/round) ----
    {
        int half = tid >> 7, t = tid & 127;
        float* a = aux + half * 1056;           // 32*33
        for (int rnd = 0; rnd < 8; rnd++) {
            int tile = rnd * 2 + half;          // 0..15
            int ic0 = (tile >> 1) * 32, ii0 = (tile & 1) * 32;
            #pragma unroll
            for (int q = 0; q < 8; q++) {
                int e = t + q * 128, y = e >> 5, xq = e & 31;
                a[y * 33 + xq] = xs[(ic0 + y) * 64 + ii0 + xq];
            }
            __syncthreads();
            #pragma unroll
            for (int q = 0; q < 8; q++) {
                int e = t + q * 128, ii = e >> 5, cc = e & 31;
                xT[(ii0 + ii) * 256 + ic0 + cc] = a[cc * 33 + ii];
            }
            __syncthreads();
        }
    }

    // ---- (it>0) load + transpose g_wt[b][j][ic] -> wts[ic][j] ----
    if (it) {
        int half = tid >> 7, t = tid & 127;
        float* a = aux + half * 1056;
        const float* wsrc = g_wt + (size_t)b * J * IC;
        for (int rnd = 0; rnd < 8; rnd++) {
            int tile = rnd * 2 + half;          // 16 tiles: 2(j) x 8(ic)
            int j0 = (tile & 1) * 32, ic0 = (tile >> 1) * 32;
            #pragma unroll
            for (int q = 0; q < 8; q++) {
                int e = t + q * 128, y = e >> 5, xq = e & 31;
                a[y * 33 + xq] = wsrc[(size_t)(j0 + y) * IC + ic0 + xq];
            }
            __syncthreads();
            #pragma unroll
            for (int q = 0; q < 8; q++) {
                int e = t + q * 128, icq = e >> 5, jj = e & 31;
                wts[(ic0 + icq) * 64 + j0 + jj] = a[jj * 33 + icq];
            }
            __syncthreads();
        }
    }

    const int ty = tid >> 4, tx = tid & 15;

    // ---- db GEMM: M=64(j) x N=64(i), K=256(ic); microtile 4x4 f32x2 ----
    if (it) {
        const int j0 = ty * 4, il0 = tx * 4;
        unsigned long long acc[4][2];
        #pragma unroll
        for (int r = 0; r < 4; r++) { acc[r][0] = 0ull; acc[r][1] = 0ull; }
        for (int k = 0; k < IC; k++) {
            float4 a4 = *reinterpret_cast<const float4*>(wts + k * 64 + j0);
            ulonglong2 b2 = *reinterpret_cast<const ulonglong2*>(xs + k * 64 + il0);
            unsigned long long ad;
            ad = dup2f(a4.x); FFMA2(acc[0][0], ad, b2.x); FFMA2(acc[0][1], ad, b2.y);
            ad = dup2f(a4.y); FFMA2(acc[1][0], ad, b2.x); FFMA2(acc[1][1], ad, b2.y);
            ad = dup2f(a4.z); FFMA2(acc[2][0], ad, b2.x); FFMA2(acc[2][1], ad, b2.y);
            ad = dup2f(a4.w); FFMA2(acc[3][0], ad, b2.x); FFMA2(acc[3][1], ad, b2.y);
        }
        const float* Lsrc = (it == 2) ? g_L : b_init;
        #pragma unroll
        for (int r = 0; r < 4; r++) {
            int j = j0 + r;
            float be = g_beta[b * J + j];
            const float* Ls = Lsrc + ((size_t)b * J + j) * NPIX + i0g + il0;
            float2 lo = unpk(acc[r][0]), hi = unpk(acc[r][1]);
            float l0 = Ls[0] + lo.x + be;
            float l1 = Ls[1] + lo.y + be;
            float l2 = Ls[2] + hi.x + be;
            float l3 = Ls[3] + hi.y + be;
            float* Ld = Lc + j * 65 + il0;
            Ld[0] = l0; Ld[1] = l1; Ld[2] = l2; Ld[3] = l3;
            if (it == 1) {
                float* Lg = g_L + ((size_t)b * J + j) * NPIX + i0g + il0;
                Lg[0] = l0; Lg[1] = l1; Lg[2] = l2; Lg[3] = l3;
            }
        }
        __syncthreads();
    }

    // ---- softmax over j per pixel i; cs[i][j] = c ----
    {
        int g = tid >> 6, i = tid & 63;
        int jlo = g * 16;
        float m = -1e30f;
        #pragma unroll
        for (int jj = 0; jj < 16; jj++)
            m = fmaxf(m, Lc[(jlo + jj) * 65 + i]);
        pm[g * 64 + i] = m;
        __syncthreads();
        m = fmaxf(fmaxf(pm[i], pm[64 + i]), fmaxf(pm[128 + i], pm[192 + i]));
        float ssum = 0.f;
        #pragma unroll
        for (int jj = 0; jj < 16; jj++) {
            float e = __expf(Lc[(jlo + jj) * 65 + i] - m);
            cs[i * 65 + jlo + jj] = e;
            ssum += e;
        }
        ps[g * 64 + i] = ssum;
        __syncthreads();
        float rd = 1.0f / (ps[i] + ps[64 + i] + ps[128 + i] + ps[192 + i]);
        #pragma unroll
        for (int jj = 0; jj < 16; jj++)
            cs[i * 65 + jlo + jj] *= rd;
    }
    __syncthreads();

    // Csum partial per j
    if (tid < J) {
        float cc = 0.f;
        #pragma unroll 8
        for (int i2 = 0; i2 < CW; i2++) cc += cs[i2 * 65 + tid];
        g_cpart[((size_t)b * NCHK + ch) * J + tid] = cc;
    }

    // ---- y GEMM: M=64(j) x N=256(ic), K=64(i); microtile 4x16 f32x2 ----
    {
        const int j0 = ty * 4, ic0 = tx * 16;
        unsigned long long acc[4][8];
        #pragma unroll
        for (int r = 0; r < 4; r++)
            #pragma unroll
            for (int p = 0; p < 8; p++) acc[r][p] = 0ull;

        for (int k = 0; k < CW; k++) {
            const float* crow = cs + k * 65 + j0;
            unsigned long long ad0 = dup2f(crow[0]);
            unsigned long long ad1 = dup2f(crow[1]);
            unsigned long long ad2 = dup2f(crow[2]);
            unsigned long long ad3 = dup2f(crow[3]);
            const ulonglong2* bq = reinterpret_cast<const ulonglong2*>(xT + k * 256 + ic0);
            ulonglong2 b0 = bq[0], b1 = bq[1], b2 = bq[2], b3 = bq[3];
            FFMA2(acc[0][0], ad0, b0.x); FFMA2(acc[0][1], ad0, b0.y);
            FFMA2(acc[0][2], ad0, b1.x); FFMA2(acc[0][3], ad0, b1.y);
            FFMA2(acc[0][4], ad0, b2.x); FFMA2(acc[0][5], ad0, b2.y);
            FFMA2(acc[0][6], ad0, b3.x); FFMA2(acc[0][7], ad0, b3.y);
            FFMA2(acc[1][0], ad1, b0.x); FFMA2(acc[1][1], ad1, b0.y);
            FFMA2(acc[1][2], ad1, b1.x); FFMA2(acc[1][3], ad1, b1.y);
            FFMA2(acc[1][4], ad1, b2.x); FFMA2(acc[1][5], ad1, b2.y);
            FFMA2(acc[1][6], ad1, b3.x); FFMA2(acc[1][7], ad1, b3.y);
            FFMA2(acc[2][0], ad2, b0.x); FFMA2(acc[2][1], ad2, b0.y);
            FFMA2(acc[2][2], ad2, b1.x); FFMA2(acc[2][3], ad2, b1.y);
            FFMA2(acc[2][4], ad2, b2.x); FFMA2(acc[2][5], ad2, b2.y);
            FFMA2(acc[2][6], ad2, b3.x); FFMA2(acc[2][7], ad2, b3.y);
            FFMA2(acc[3][0], ad3, b0.x); FFMA2(acc[3][1], ad3, b0.y);
            FFMA2(acc[3][2], ad3, b1.x); FFMA2(acc[3][3], ad3, b1.y);
            FFMA2(acc[3][4], ad3, b2.x); FFMA2(acc[3][5], ad3, b2.y);
            FFMA2(acc[3][6], ad3, b3.x); FFMA2(acc[3][7], ad3, b3.y);
        }
        float* ybase = g_ypart + (((size_t)b * NCHK + ch) * J + j0) * IC + ic0;
        #pragma unroll
        for (int r = 0; r < 4; r++) {
            float* yr = ybase + (size_t)r * IC;
            #pragma unroll
            for (int p = 0; p < 4; p++) {
                float2 e0 = unpk(acc[r][2 * p]);
                float2 e1 = unpk(acc[r][2 * p + 1]);
                float4 v4 = make_float4(e0.x, e0.y, e1.x, e1.y);
                *reinterpret_cast<float4*>(yr + p * 4) = v4;
            }
        }
    }
}

// ---------------------------------------------------------------------------
// S kernel: one CTA per (j, 16-b group). Reduce y, s = W_j.y + Wb.C, squash,
// then wt[ic] = sum_d v_d W_j[d][ic] and beta = sum_d v_d Wb[jd].
// ---------------------------------------------------------------------------
__global__ __launch_bounds__(256) void s_kernel(
    const float* __restrict__ W, const float* __restrict__ Wb,
    float* __restrict__ out, int final_it)
{
    __shared__ float Wj[D2 * IC];      // 32 KB
    __shared__ float ysm[IC];
    __shared__ float ssm[D2];
    __shared__ float vsm[D2];
    __shared__ float Wbj[D2];

    const int j   = blockIdx.x;
    const int bg  = blockIdx.y;
    const int tid = threadIdx.x;
    const int w   = tid >> 5;
    const int lane = tid & 31;

    for (int e = tid; e < D2 * IC; e += 256)
        Wj[e] = W[(size_t)j * D2 * IC + e];
    if (tid < D2) Wbj[tid] = Wb[j * D2 + tid];
    __syncthreads();

    for (int bi = 0; bi < 16; bi++) {
        int b = bg * 16 + bi;

        // reduce y over chunks
        float yv = 0.f;
        const float* yp = g_ypart + (((size_t)b * NCHK) * J + j) * IC + tid;
        #pragma unroll
        for (int c = 0; c < NCHK; c++)
            yv += yp[(size_t)c * J * IC];
        ysm[tid] = yv;

        // C (redundant per-thread, L1-cached)
        const float* cp = g_cpart + ((size_t)b * NCHK) * J + j;
        float C = cp[0] + cp[J] + cp[2 * J] + cp[3 * J];
        __syncthreads();

        // s[d]: warp w computes d = 4w..4w+3
        #pragma unroll
        for (int dd = 0; dd < 4; dd++) {
            int d = w * 4 + dd;
            float p = 0.f;
            #pragma unroll
            for (int q = 0; q < 8; q++)
                p = fmaf(Wj[d * IC + lane + q * 32], ysm[lane + q * 32], p);
            #pragma unroll
            for (int o = 16; o; o >>= 1) p += __shfl_xor_sync(0xFFFFFFFFu, p, o);
            if (lane == 0) ssm[d] = p + Wbj[d] * C;
        }
        __syncthreads();

        // squash + beta by warp 0
        if (w == 0) {
            float sv = ssm[lane];
            float sq = sv * sv;
            #pragma unroll
            for (int o = 16; o; o >>= 1) sq += __shfl_xor_sync(0xFFFFFFFFu, sq, o);
            float scale = (sq / (1.0f + sq)) * rsqrtf(sq + 1e-8f);
            float vv = scale * sv;
            vsm[lane] = vv;
            if (final_it) out[((size_t)b * J + j) * D2 + lane] = vv;
            float bt = vv * Wbj[lane];
            #pragma unroll
            for (int o = 16; o; o >>= 1) bt += __shfl_xor_sync(0xFFFFFFFFu, bt, o);
            if (lane == 0) g_beta[b * J + j] = bt;
        }
        __syncthreads();

        if (!final_it) {
            float wv = 0.f;
            #pragma unroll
            for (int d = 0; d < D2; d++)
                wv = fmaf(vsm[d], Wj[d * IC + tid], wv);
            g_wt[((size_t)b * J + j) * IC + tid] = wv;
        }
        __syncthreads();
    }
}

// ---------------------------------------------------------------------------
// Launch (6 kernels, graph-capturable, allocation-free)
// Inputs: x[64,256,16,16] f32, b_init[64,64,256] f32, W[2048,256] f32, Wb[2048] f32
// Output: v[64,64,32] f32
// ---------------------------------------------------------------------------
extern "C" void kernel_launch(void* const* d_in, const int* in_sizes, int n_in,
                              void* d_out, int out_size)
{
    const float* x      = (const float*)d_in[0];
    const float* b_init = (const float*)d_in[1];
    const float* W      = (const float*)d_in[2];
    const float* Wb     = (const float*)d_in[3];
    float* out = (float*)d_out;

    const int smem = SM_FLOATS * (int)sizeof(float);   // 231,936 B
    cudaFuncSetAttribute(yd_kernel, cudaFuncAttributeMaxDynamicSharedMemorySize, smem);

    dim3 ygrid(NCHK, BS);      // 4 x 64
    dim3 sgrid(J, 4);          // 64 x 4

    yd_kernel<<<ygrid, 256, smem>>>(x, b_init, 0);
    s_kernel<<<sgrid, 256>>>(W, Wb, out, 0);
    yd_kernel<<<ygrid, 256, smem>>>(x, b_init, 1);
    s_kernel<<<sgrid, 256>>>(W, Wb, out, 0);
    yd_kernel<<<ygrid, 256, smem>>>(x, b_init, 2);
    s_kernel<<<sgrid, 256>>>(W, Wb, out, 1);
}

// round 11
// speedup vs baseline: 2.4382x; 1.3387x over previous
#include <cuda_runtime.h>
#include <cstdint>

// Problem constants
#define BS   64
#define IC   256     // in_dim
#define NPIX 256     // pixels (I)
#define J    64      // out caps
#define D2   32      // dim per cap
#define NCHK 4       // i-chunks per batch in YD
#define CW   64      // chunk width (pixels)

// Global scratch (pred never materialized)
__device__ float g_L[(size_t)BS * J * NPIX];            // logits after iter-1
__device__ float g_ypart[(size_t)BS * NCHK * J * IC];   // [b][ch][j][ic]
__device__ float g_cpart[(size_t)BS * NCHK * J];        // [b][ch][j]
__device__ float g_wt[(size_t)BS * J * IC];             // [b][j][ic]
__device__ float g_beta[(size_t)BS * J];                // [b][j]

// ---------------------------------------------------------------------------
// f32x2 helpers
// ---------------------------------------------------------------------------
#define FFMA2(acc, aa, bb) \
    asm("fma.rn.f32x2 %0, %1, %2, %0;" : "+l"(acc) : "l"(aa), "l"(bb))
__device__ __forceinline__ unsigned long long dup2f(float s) {
    unsigned long long d;
    asm("mov.b64 %0, {%1, %1};" : "=l"(d) : "f"(s));
    return d;
}
__device__ __forceinline__ float2 unpk(unsigned long long v) {
    float2 r;
    asm("mov.b64 {%0, %1}, %2;" : "=f"(r.x), "=f"(r.y) : "l"(v));
    return r;
}

// SMEM float offsets for yd_kernel
#define CSP    68                // cs row stride: multiple of 4 -> aligned float4
#define XS_O   0                 // xs [ic=256][i=64]        16384
#define XT_O   16384             // xT [i=64][ic=256]        16384
#define WR_O   32768             // wt_raw [j=64][ic=256]    16384
#define CS_O   49152             // cs [i=64][j pad 68]      4352  (aux aliases)
#define LC_O   (CS_O + 64 * CSP) // Lc [j=64][i pad 65]      4160
#define SM_FLOATS (LC_O + 64 * 65)   // 57664 floats = 230,656 B

// ---------------------------------------------------------------------------
// YD kernel: one CTA per (i-chunk, b), 512 threads.
// it==0:  Lc = b_init;                          softmax; y partials
// it==1:  db = wt.x+beta; L=b_init+db (-> g_L); softmax; y partials
// it==2:  db = wt.x+beta; L=g_L+db;             softmax; y partials
// ---------------------------------------------------------------------------
__global__ __launch_bounds__(512, 1) void yd_kernel(
    const float* __restrict__ x, const float* __restrict__ b_init, int it)
{
    extern __shared__ float sm[];
    float* xs = sm + XS_O;
    float* xT = sm + XT_O;
    float* wr = sm + WR_O;
    float* cs = sm + CS_O;
    float* Lc = sm + LC_O;
    float* aux = sm + CS_O;          // 2 x (32x33) = 2112 floats, pre-cs only

    const int ch  = blockIdx.x;
    const int b   = blockIdx.y;
    const int i0g = ch * CW;
    const int tid = threadIdx.x;

    // ---- loads (coalesced) ----
    const float* xb = x + (size_t)b * IC * NPIX + i0g;
    for (int e = tid; e < IC * CW; e += 512) {
        int ic = e >> 6, il = e & 63;
        xs[ic * 64 + il] = xb[(size_t)ic * NPIX + il];
    }
    if (it) {
        const float* wsrc = g_wt + (size_t)b * J * IC;
        for (int e = tid; e < J * IC; e += 512)
            wr[e] = wsrc[e];
    } else {
        for (int e = tid; e < J * CW; e += 512) {
            int j = e >> 6, il = e & 63;
            Lc[j * 65 + il] = b_init[((size_t)b * J + j) * NPIX + i0g + il];
        }
    }
    __syncthreads();

    // ---- transpose xs -> xT via two padded 32x32 tiles per round ----
    {
        int half = tid >> 8, t = tid & 255;
        float* a = aux + half * 1056;
        for (int rnd = 0; rnd < 8; rnd++) {
            int tile = rnd * 2 + half;              // 0..15
            int ic0 = (tile >> 1) * 32, ii0 = (tile & 1) * 32;
            #pragma unroll
            for (int q = 0; q < 4; q++) {
                int e = t + q * 256, yq = e >> 5, xq = e & 31;
                a[yq * 33 + xq] = xs[(ic0 + yq) * 64 + ii0 + xq];
            }
            __syncthreads();
            #pragma unroll
            for (int q = 0; q < 4; q++) {
                int e = t + q * 256, ii = e >> 5, cc = e & 31;
                xT[(ii0 + ii) * 256 + ic0 + cc] = a[cc * 33 + ii];
            }
            __syncthreads();
        }
    }

    // ---- db GEMM: M=64(j) x N=64(i), K=256(ic); tile 2j x 4i ----
    if (it) {
        const int ty = tid >> 4, tx = tid & 15;     // ty 0..31, tx 0..15
        const int j0 = ty * 2, il0 = tx * 4;
        unsigned long long acc[2][2] = {{0ull, 0ull}, {0ull, 0ull}};
        const float* w0p = wr + j0 * IC;
        const float* w1p = wr + (j0 + 1) * IC;
        #pragma unroll 4
        for (int k = 0; k < IC; k++) {
            ulonglong2 b2 = *reinterpret_cast<const ulonglong2*>(xs + k * 64 + il0);
            unsigned long long ad0 = dup2f(w0p[k]);
            unsigned long long ad1 = dup2f(w1p[k]);
            FFMA2(acc[0][0], ad0, b2.x); FFMA2(acc[0][1], ad0, b2.y);
            FFMA2(acc[1][0], ad1, b2.x); FFMA2(acc[1][1], ad1, b2.y);
        }
        const float* Lsrc = (it == 2) ? g_L : b_init;
        #pragma unroll
        for (int r = 0; r < 2; r++) {
            int j = j0 + r;
            float be = g_beta[b * J + j];
            const float* Ls = Lsrc + ((size_t)b * J + j) * NPIX + i0g + il0;
            float2 lo = unpk(acc[r][0]), hi = unpk(acc[r][1]);
            float l0 = Ls[0] + lo.x + be;
            float l1 = Ls[1] + lo.y + be;
            float l2 = Ls[2] + hi.x + be;
            float l3 = Ls[3] + hi.y + be;
            float* Ld = Lc + j * 65 + il0;
            Ld[0] = l0; Ld[1] = l1; Ld[2] = l2; Ld[3] = l3;
            if (it == 1) {
                float* Lg = g_L + ((size_t)b * J + j) * NPIX + i0g + il0;
                Lg[0] = l0; Lg[1] = l1; Lg[2] = l2; Lg[3] = l3;
            }
        }
        __syncthreads();
    }

    // ---- softmax over j per pixel: 8 threads per pixel, shfl reduce ----
    {
        int i = tid >> 3, sub = tid & 7, jb = sub * 8;
        float m = -1e30f;
        #pragma unroll
        for (int jj = 0; jj < 8; jj++)
            m = fmaxf(m, Lc[(jb + jj) * 65 + i]);
        #pragma unroll
        for (int o = 1; o < 8; o <<= 1)
            m = fmaxf(m, __shfl_xor_sync(0xFFFFFFFFu, m, o));
        float ssum = 0.f;
        #pragma unroll
        for (int jj = 0; jj < 8; jj++) {
            float e = __expf(Lc[(jb + jj) * 65 + i] - m);
            cs[i * CSP + jb + jj] = e;
            ssum += e;
        }
        #pragma unroll
        for (int o = 1; o < 8; o <<= 1)
            ssum += __shfl_xor_sync(0xFFFFFFFFu, ssum, o);
        float rd = 1.0f / ssum;
        #pragma unroll
        for (int jj = 0; jj < 8; jj++)
            cs[i * CSP + jb + jj] *= rd;
    }
    __syncthreads();

    // ---- Csum partial per j ----
    if (tid < J) {
        float cc = 0.f;
        #pragma unroll 8
        for (int i2 = 0; i2 < CW; i2++) cc += cs[i2 * CSP + tid];
        g_cpart[((size_t)b * NCHK + ch) * J + tid] = cc;
    }

    // ---- y GEMM: M=64(j) x N=256(ic), K=64(i); tile 4j x 8ic ----
    {
        const int ty = tid >> 5, tx = tid & 31;     // ty 0..15, tx 0..31
        const int j0 = ty * 4, ic0 = tx * 8;
        unsigned long long acc[4][4];
        #pragma unroll
        for (int r = 0; r < 4; r++)
            #pragma unroll
            for (int p = 0; p < 4; p++) acc[r][p] = 0ull;

        for (int k = 0; k < CW; k++) {
            // CSP = 68 ≡ 0 mod 4 -> 16B-aligned float4 (R10 bug was stride 65)
            float4 c4 = *reinterpret_cast<const float4*>(cs + k * CSP + j0);
            const ulonglong2* bq = reinterpret_cast<const ulonglong2*>(xT + k * 256 + ic0);
            ulonglong2 b0 = bq[0], b1 = bq[1];
            unsigned long long ad;
            ad = dup2f(c4.x);
            FFMA2(acc[0][0], ad, b0.x); FFMA2(acc[0][1], ad, b0.y);
            FFMA2(acc[0][2], ad, b1.x); FFMA2(acc[0][3], ad, b1.y);
            ad = dup2f(c4.y);
            FFMA2(acc[1][0], ad, b0.x); FFMA2(acc[1][1], ad, b0.y);
            FFMA2(acc[1][2], ad, b1.x); FFMA2(acc[1][3], ad, b1.y);
            ad = dup2f(c4.z);
            FFMA2(acc[2][0], ad, b0.x); FFMA2(acc[2][1], ad, b0.y);
            FFMA2(acc[2][2], ad, b1.x); FFMA2(acc[2][3], ad, b1.y);
            ad = dup2f(c4.w);
            FFMA2(acc[3][0], ad, b0.x); FFMA2(acc[3][1], ad, b0.y);
            FFMA2(acc[3][2], ad, b1.x); FFMA2(acc[3][3], ad, b1.y);
        }
        float* ybase = g_ypart + (((size_t)b * NCHK + ch) * J + j0) * IC + ic0;
        #pragma unroll
        for (int r = 0; r < 4; r++) {
            float* yr = ybase + (size_t)r * IC;
            #pragma unroll
            for (int p = 0; p < 2; p++) {
                float2 e0 = unpk(acc[r][2 * p]);
                float2 e1 = unpk(acc[r][2 * p + 1]);
                *reinterpret_cast<float4*>(yr + p * 4) =
                    make_float4(e0.x, e0.y, e1.x, e1.y);
            }
        }
    }
}

// ---------------------------------------------------------------------------
// S kernel: one CTA per (j, b-group of 4). Reduce y, s = W_j.y + Wb.C,
// squash, then wt = sum_d v_d W_j[d,:] and beta = sum_d v_d Wb.
// ---------------------------------------------------------------------------
__global__ __launch_bounds__(256) void s_kernel(
    const float* __restrict__ W, const float* __restrict__ Wb,
    float* __restrict__ out, int final_it)
{
    __shared__ float Wj[D2 * IC];      // 32 KB
    __shared__ float ysm[IC];
    __shared__ float ssm[D2];
    __shared__ float vsm[D2];
    __shared__ float Wbj[D2];

    const int j    = blockIdx.x;
    const int bg   = blockIdx.y;
    const int tid  = threadIdx.x;
    const int w    = tid >> 5;
    const int lane = tid & 31;

    for (int e = tid; e < D2 * IC; e += 256)
        Wj[e] = W[(size_t)j * D2 * IC + e];
    if (tid < D2) Wbj[tid] = Wb[j * D2 + tid];
    __syncthreads();

    #pragma unroll
    for (int bi = 0; bi < 4; bi++) {
        int b = bg * 4 + bi;

        // reduce y over chunks
        float yv = 0.f;
        const float* yp = g_ypart + (((size_t)b * NCHK) * J + j) * IC + tid;
        #pragma unroll
        for (int c = 0; c < NCHK; c++)
            yv += yp[(size_t)c * J * IC];
        ysm[tid] = yv;

        const float* cp = g_cpart + ((size_t)b * NCHK) * J + j;
        float C = cp[0] + cp[J] + cp[2 * J] + cp[3 * J];
        __syncthreads();

        // s[d]: warp w computes d = 4w..4w+3
        #pragma unroll
        for (int dd = 0; dd < 4; dd++) {
            int d = w * 4 + dd;
            float p = 0.f;
            #pragma unroll
            for (int q = 0; q < 8; q++)
                p = fmaf(Wj[d * IC + lane + q * 32], ysm[lane + q * 32], p);
            #pragma unroll
            for (int o = 16; o; o >>= 1) p += __shfl_xor_sync(0xFFFFFFFFu, p, o);
            if (lane == 0) ssm[d] = p + Wbj[d] * C;
        }
        __syncthreads();

        // squash + beta (warp 0)
        if (w == 0) {
            float sv = ssm[lane];
            float sq = sv * sv;
            #pragma unroll
            for (int o = 16; o; o >>= 1) sq += __shfl_xor_sync(0xFFFFFFFFu, sq, o);
            float scale = (sq / (1.0f + sq)) * rsqrtf(sq + 1e-8f);
            float vv = scale * sv;
            vsm[lane] = vv;
            if (final_it) out[((size_t)b * J + j) * D2 + lane] = vv;
            float bt = vv * Wbj[lane];
            #pragma unroll
            for (int o = 16; o; o >>= 1) bt += __shfl_xor_sync(0xFFFFFFFFu, bt, o);
            if (lane == 0) g_beta[b * J + j] = bt;
        }
        __syncthreads();

        if (!final_it) {
            float wv = 0.f;
            #pragma unroll
            for (int d = 0; d < D2; d++)
                wv = fmaf(vsm[d], Wj[d * IC + tid], wv);
            g_wt[((size_t)b * J + j) * IC + tid] = wv;
        }
        __syncthreads();
    }
}

// ---------------------------------------------------------------------------
// Launch (6 kernels, graph-capturable, allocation-free)
// Inputs: x[64,256,16,16] f32, b_init[64,64,256] f32, W[2048,256] f32, Wb[2048] f32
// Output: v[64,64,32] f32
// ---------------------------------------------------------------------------
extern "C" void kernel_launch(void* const* d_in, const int* in_sizes, int n_in,
                              void* d_out, int out_size)
{
    const float* x      = (const float*)d_in[0];
    const float* b_init = (const float*)d_in[1];
    const float* W      = (const float*)d_in[2];
    const float* Wb     = (const float*)d_in[3];
    float* out = (float*)d_out;

    const int smem = SM_FLOATS * (int)sizeof(float);   // 230,656 B
    cudaFuncSetAttribute(yd_kernel, cudaFuncAttributeMaxDynamicSharedMemorySize, smem);

    dim3 ygrid(NCHK, BS);      // 4 x 64 = 256 CTAs
    dim3 sgrid(J, 16);         // 64 x 16 = 1024 CTAs

    yd_kernel<<<ygrid, 512, smem>>>(x, b_init, 0);
    s_kernel<<<sgrid, 256>>>(W, Wb, out, 0);
    yd_kernel<<<ygrid, 512, smem>>>(x, b_init, 1);
    s_kernel<<<sgrid, 256>>>(W, Wb, out, 0);
    yd_kernel<<<ygrid, 512, smem>>>(x, b_init, 2);
    s_kernel<<<sgrid, 256>>>(W, Wb, out, 1);
}